// round 9
// baseline (speedup 1.0000x reference)
#include <cuda_runtime.h>
#include <math.h>

#define BS   16
#define NP   4000
#define CC   80
#define GG   300
#define KTOP 13
#define WPB  8            // warps per block in assign
#define JPT  125          // elements per lane (32*125 = 4000)

// Scratch (device globals; zero-initialized at load)
__device__ float g_scores_t[BS * CC * NP];       // sigmoid(logits) transposed [b][c][n]
__device__ unsigned long long g_key[BS * NP];    // packed (mapped_overlap, ~g) per pred

struct Box { float x1, y1, x2, y2, area; };

__device__ __forceinline__ Box toxyxy(float4 b) {
    Box r;
    r.x1 = b.x - 0.5f * b.z;
    r.y1 = b.y - 0.5f * b.w;
    r.x2 = b.x + 0.5f * b.z;
    r.y2 = b.y + 0.5f * b.w;
    r.area = (r.x2 - r.x1) * (r.y2 - r.y1);
    return r;
}

// EXACT mirror of the reference arithmetic (order of ops matters for ranking):
//   iou = inter/union;  giou = iou - (area_e - union)/area_e;  return -giou
__device__ __forceinline__ float neg_giou(const Box& a, const Box& b) {
    float ltx = fmaxf(a.x1, b.x1), lty = fmaxf(a.y1, b.y1);
    float rbx = fminf(a.x2, b.x2), rby = fminf(a.y2, b.y2);
    float wi = fmaxf(rbx - ltx, 0.f), hi = fmaxf(rby - lty, 0.f);
    float inter = wi * hi;
    float uni = a.area + b.area - inter;
    float iou = inter / uni;
    float lex = fminf(a.x1, b.x1), ley = fminf(a.y1, b.y1);
    float rex = fmaxf(a.x2, b.x2), rey = fmaxf(a.y2, b.y2);
    float we = fmaxf(rex - lex, 0.f), he = fmaxf(rey - ley, 0.f);
    float ae = we * he;
    float giou = iou - (ae - uni) / ae;
    return -giou;
}

__device__ __forceinline__ float pow6(float x) {
    float x2 = x * x;
    return x2 * x2 * x2;
}

// monotone map float -> u32 (order-preserving as unsigned), and inverse
__device__ __forceinline__ unsigned int fmap(float f) {
    unsigned int u = __float_as_uint(f);
    return (u & 0x80000000u) ? ~u : (u | 0x80000000u);
}
__device__ __forceinline__ float fmap_inv(unsigned int m) {
    unsigned int u = (m & 0x80000000u) ? (m & 0x7fffffffu) : ~m;
    return __uint_as_float(u);
}
__device__ __forceinline__ unsigned long long pack_key(float v, unsigned int idx) {
    return ((unsigned long long)fmap(v) << 32) | (unsigned long long)(0xffffffffu - idx);
}

__device__ __forceinline__ unsigned long long warp_max64(unsigned long long v) {
#pragma unroll
    for (int off = 16; off; off >>= 1) {
        unsigned long long o = __shfl_xor_sync(0xffffffffu, v, off);
        if (o > v) v = o;
    }
    return v;
}

// ---------------------------------------------------------------------------
// Kernel 1: sigmoid + transpose logits [b][n][c] -> scores_t [b][c][n]
// ---------------------------------------------------------------------------
__global__ void sig_transpose_kernel(const float* __restrict__ logits) {
    __shared__ float tile[32][33];
    int b = blockIdx.z;
    int n0 = blockIdx.x * 32, c0 = blockIdx.y * 32;
    int tx = threadIdx.x, ty = threadIdx.y;
#pragma unroll
    for (int i = 0; i < 4; i++) {
        int c = c0 + tx;
        int n = n0 + ty + i * 8;
        float v = 0.f;
        if (c < CC) v = logits[((size_t)b * NP + n) * CC + c];
        tile[ty + i * 8][tx] = 1.f / (1.f + expf(-v));
    }
    __syncthreads();
#pragma unroll
    for (int i = 0; i < 4; i++) {
        int n = n0 + tx;
        int c = c0 + ty + i * 8;
        if (c < CC) g_scores_t[((size_t)b * CC + c) * NP + n] = tile[tx][ty + i * 8];
    }
}

// ---------------------------------------------------------------------------
// Kernel 2: warp-per-(b,g). Per-lane top-4 in registers (packed u64 keys,
// threshold kept in mapped-u32 domain); 13 rounds of warp max-reduce;
// cooperative recompute-rescan only when a lane's cache empties.
// ---------------------------------------------------------------------------
__global__ void __launch_bounds__(WPB * 32) assign_kernel(
    const float4* __restrict__ pred_boxes,
    const float4* __restrict__ gt_boxes,
    const int* __restrict__ gt_labels)
{
    __shared__ int s_cons[WPB][16];

    int wid  = threadIdx.x >> 5;
    int lane = threadIdx.x & 31;
    int p = blockIdx.x * WPB + wid;      // (b,g) pair id, 0..4799
    int b = p / GG;
    int g = p - b * GG;

    Box gb = toxyxy(gt_boxes[b * GG + g]);
    int label = gt_labels[b * GG + g];
    const float*  srow = g_scores_t + ((size_t)b * CC + label) * NP;
    const float4* pb   = pred_boxes + (size_t)b * NP;

    // ---- compute phase: stream 125 elements, maintain sorted top-4 keys ----
    unsigned long long k1 = 0ull, k2 = 0ull, k3 = 0ull, k4 = 0ull;
    unsigned int m4 = 0u;    // mapped value of k4's alignment (monotone threshold)

#pragma unroll 5
    for (int j = 0; j < JPT; j++) {
        int n = lane + j * 32;
        Box pbox = toxyxy(pb[n]);
        float ov = neg_giou(pbox, gb);
        float al = __ldg(srow + n) * pow6(ov);
        unsigned int ma = fmap(al);
        if (ma >= m4) {
            unsigned long long key = ((unsigned long long)ma << 32)
                                   | (unsigned long long)(0xffffffffu - (unsigned)n);
            if (key > k4) {
                if (key > k3) {
                    k4 = k3;
                    if (key > k2) { k3 = k2; if (key > k1) { k2 = k1; k1 = key; } else k2 = key; }
                    else k3 = key;
                } else k4 = key;
                m4 = (unsigned int)(k4 >> 32);
            }
        }
    }

    unsigned long long* keyb = g_key + (size_t)b * NP;

    // ---- selection phase: 13 rounds, warp-local ----
    for (int k = 0; k < KTOP; k++) {
        unsigned long long w = warp_max64(k1);
        if ((unsigned int)(w >> 32) <= 0x80000000u) break;   // best alignment <= 0

        bool owner = (k1 == w);
        if (owner) {
            int n = (int)(0xffffffffu - (unsigned int)w);
            Box pbox = toxyxy(pb[n]);
            float ov = neg_giou(pbox, gb);
            atomicMax(keyb + n, pack_key(ov, (unsigned)g));
            s_cons[wid][k] = n;
            k1 = k2; k2 = k3; k3 = k4; k4 = 0ull;
        }
        __syncwarp(0xffffffffu);

        if (k < KTOP - 1) {
            unsigned need = __ballot_sync(0xffffffffu, owner && k1 == 0ull);
            if (need) {
                int ol = __ffs((int)need) - 1;     // exhausted owner lane
                unsigned long long best = 0ull;
#pragma unroll
                for (int m = 0; m < 4; m++) {
                    int j = lane + m * 32;
                    if (j < JPT) {
                        int n = ol + j * 32;
                        bool cons = false;
                        for (int t = 0; t <= k; t++)
                            if (s_cons[wid][t] == n) cons = true;
                        if (!cons) {
                            Box pbox = toxyxy(pb[n]);
                            float ov = neg_giou(pbox, gb);
                            float al = __ldg(srow + n) * pow6(ov);
                            unsigned long long key = pack_key(al, (unsigned)n);
                            if (key > best) best = key;
                        }
                    }
                }
                best = warp_max64(best);
                if (lane == ol) k1 = best;
            }
        }
    }
}

// ---------------------------------------------------------------------------
// Kernel 3: finalize — decode winner from key (ov is embedded), reset key.
// ---------------------------------------------------------------------------
__global__ void finalize_kernel(
    const int* __restrict__ gt_labels,
    float* __restrict__ out)
{
    int i = blockIdx.x * blockDim.x + threadIdx.x;
    if (i >= BS * NP) return;
    int b = i / NP;
    int n = i - b * NP;

    unsigned long long key = g_key[i];
    g_key[i] = 0ull;    // reset for next graph replay
    float inds = 0.f, lab = -1.f, met = 0.f;
    if (key != 0ull) {
        int g = (int)(0xffffffffu - (unsigned)(key & 0xffffffffu));
        float ov = fmap_inv((unsigned int)(key >> 32));
        int label = gt_labels[b * GG + g];
        float s = g_scores_t[((size_t)b * CC + label) * NP + n];
        met = s * pow6(ov);
        inds = (float)(g + 1);
        lab = (float)label;
    }
    out[i] = inds;
    out[BS * NP + i] = lab;
    out[2 * BS * NP + i] = met;
}

// ---------------------------------------------------------------------------
extern "C" void kernel_launch(void* const* d_in, const int* in_sizes, int n_in,
                              void* d_out, int out_size) {
    const float*  logits     = (const float*)d_in[0];
    const float4* pred_boxes = (const float4*)d_in[1];
    const float4* gt_boxes   = (const float4*)d_in[2];
    const int*    gt_labels  = (const int*)d_in[3];
    float* out = (float*)d_out;

    dim3 tgrid(NP / 32, (CC + 31) / 32, BS);
    sig_transpose_kernel<<<tgrid, dim3(32, 8)>>>(logits);
    assign_kernel<<<(BS * GG) / WPB, WPB * 32>>>(pred_boxes, gt_boxes, gt_labels);
    finalize_kernel<<<(BS * NP + 255) / 256, 256>>>(gt_labels, out);
}